// round 1
// baseline (speedup 1.0000x reference)
#include <cuda_runtime.h>

#define NB 8192
#define ND 512
#define NK 2048
#define NL 4
#define EPSN 1e-5f
#define TEMP_MIN 0.01f

// Scratch (no allocations allowed)
static __device__ float g_y[NB * ND];        // proj output pre-LN
static __device__ float g_x[NB * ND];        // relu(LN(...)) output
static __device__ float g_rn[NB];            // ||s0 * x_b||^2
static __device__ float g_cn[NL * NK];       // ||cb[l][k]||^2

// ---------------------------------------------------------------------------
// Block reduce (sum of two values), 256 threads = 8 warps. Broadcasts result.
// ---------------------------------------------------------------------------
__device__ __forceinline__ void block_reduce2(float& a, float& b, float* sbuf) {
#pragma unroll
    for (int o = 16; o > 0; o >>= 1) {
        a += __shfl_xor_sync(0xffffffffu, a, o);
        b += __shfl_xor_sync(0xffffffffu, b, o);
    }
    int w = threadIdx.x >> 5;
    if ((threadIdx.x & 31) == 0) { sbuf[w] = a; sbuf[8 + w] = b; }
    __syncthreads();
    float ta = 0.f, tb = 0.f;
#pragma unroll
    for (int i = 0; i < 8; i++) { ta += sbuf[i]; tb += sbuf[8 + i]; }
    a = ta; b = tb;
    __syncthreads();  // allow sbuf reuse
}

// ---------------------------------------------------------------------------
// Codebook row norms: one warp per (l,k) row of 512 floats.
// ---------------------------------------------------------------------------
__global__ void __launch_bounds__(256) cbnorm_kernel(const float* __restrict__ cb,
                                                     float* __restrict__ cn) {
    int row  = blockIdx.x * 8 + (threadIdx.x >> 5);
    int lane = threadIdx.x & 31;
    const float* p = cb + (size_t)row * ND;
    float s = 0.f;
#pragma unroll
    for (int i = 0; i < 4; i++) {
        float4 v = *(const float4*)&p[(lane + i * 32) * 4];
        s += v.x * v.x + v.y * v.y + v.z * v.z + v.w * v.w;
    }
#pragma unroll
    for (int o = 16; o > 0; o >>= 1) s += __shfl_xor_sync(0xffffffffu, s, o);
    if (lane == 0) cn[row] = s;
}

// ---------------------------------------------------------------------------
// Fused LayerNorm(affine)+ReLU on proj output, plus second LayerNorm (no
// affine) of s0*x for quantized_sum, plus row norm ||s0*x||^2.
// One block (256 threads) per row; each thread owns 2 elements.
// ---------------------------------------------------------------------------
__global__ void __launch_bounds__(256) ln_kernel(const float* __restrict__ lng,
                                                 const float* __restrict__ lnb,
                                                 const float* __restrict__ scales,
                                                 float* __restrict__ q_out) {
    __shared__ float red[16];
    int b = blockIdx.x;
    int t = threadIdx.x;
    const float* y = g_y + (size_t)b * ND;
    float2 v = *(const float2*)&y[t * 2];

    float s = v.x + v.y;
    float s2 = v.x * v.x + v.y * v.y;
    block_reduce2(s, s2, red);
    float mu  = s * (1.0f / ND);
    float var = s2 * (1.0f / ND) - mu * mu;
    float rstd = rsqrtf(var + EPSN);

    float g0 = lng[t * 2], g1 = lng[t * 2 + 1];
    float b0 = lnb[t * 2], b1 = lnb[t * 2 + 1];
    float x0 = fmaxf((v.x - mu) * rstd * g0 + b0, 0.0f);
    float x1 = fmaxf((v.y - mu) * rstd * g1 + b1, 0.0f);
    float2 xo; xo.x = x0; xo.y = x1;
    *(float2*)&g_x[(size_t)b * ND + t * 2] = xo;

    float s0 = scales[0];
    float v0 = s0 * x0, v1 = s0 * x1;
    float ss = v0 + v1, ss2 = v0 * v0 + v1 * v1;
    block_reduce2(ss, ss2, red);
    if (t == 0) g_rn[b] = ss2;
    float mu2  = ss * (1.0f / ND);
    float var2 = ss2 * (1.0f / ND) - mu2 * mu2;
    float rstd2 = rsqrtf(var2 + EPSN);
    float2 qo;
    qo.x = (v0 - mu2) * rstd2;
    qo.y = (v1 - mu2) * rstd2;
    *(float2*)&q_out[(size_t)b * ND + t * 2] = qo;
}

// ---------------------------------------------------------------------------
// Tiled SGEMM, C = A[M,Kd] * B[N,Kd]^T   (NT).  BM=128, BN=64, BK=16.
// 256 threads, 8x4 accumulators per thread.
// MODE 0: C[r*N+c] = acc + bias[c]       (proj)
// MODE 1: logits epilogue into out[r*(NL*NK) + c]
// ---------------------------------------------------------------------------
template <int MODE>
__global__ void __launch_bounds__(256, 2) gemm_nt(const float* __restrict__ A,
                                                  const float* __restrict__ Bmat,
                                                  float* __restrict__ Cout, int N, int Kd,
                                                  const float* __restrict__ bias,
                                                  const float* __restrict__ rn,
                                                  const float* __restrict__ cn,
                                                  const float* __restrict__ scales,
                                                  const float* __restrict__ temp) {
    __shared__ __align__(16) float As[16][132];
    __shared__ __align__(16) float Bs[16][68];
    const int tid = threadIdx.x;
    const int bm = blockIdx.y * 128;
    const int bn = blockIdx.x * 64;
    const int tx = tid & 15;   // N direction, 16 x TN=4 = 64
    const int ty = tid >> 4;   // M direction, 16 x TM=8 = 128

    float acc[8][4];
#pragma unroll
    for (int i = 0; i < 8; i++)
#pragma unroll
        for (int j = 0; j < 4; j++) acc[i][j] = 0.f;

    const int lrow = tid >> 2;          // 0..63
    const int lcol = (tid & 3) << 2;    // 0,4,8,12
    const float* Aptr = A + (size_t)(bm + lrow) * Kd + lcol;
    const float* Bptr = Bmat + (size_t)(bn + lrow) * Kd + lcol;

    for (int k0 = 0; k0 < Kd; k0 += 16) {
        float4 a0 = *(const float4*)(Aptr + k0);
        float4 a1 = *(const float4*)(Aptr + (size_t)64 * Kd + k0);
        float4 b0 = *(const float4*)(Bptr + k0);
        As[lcol + 0][lrow] = a0.x;  As[lcol + 1][lrow] = a0.y;
        As[lcol + 2][lrow] = a0.z;  As[lcol + 3][lrow] = a0.w;
        As[lcol + 0][lrow + 64] = a1.x;  As[lcol + 1][lrow + 64] = a1.y;
        As[lcol + 2][lrow + 64] = a1.z;  As[lcol + 3][lrow + 64] = a1.w;
        Bs[lcol + 0][lrow] = b0.x;  Bs[lcol + 1][lrow] = b0.y;
        Bs[lcol + 2][lrow] = b0.z;  Bs[lcol + 3][lrow] = b0.w;
        __syncthreads();
#pragma unroll
        for (int kk = 0; kk < 16; kk++) {
            float4 av0 = *(const float4*)&As[kk][ty * 8];
            float4 av1 = *(const float4*)&As[kk][ty * 8 + 4];
            float4 bv  = *(const float4*)&Bs[kk][tx * 4];
            float a[8] = {av0.x, av0.y, av0.z, av0.w, av1.x, av1.y, av1.z, av1.w};
            float bb[4] = {bv.x, bv.y, bv.z, bv.w};
#pragma unroll
            for (int i = 0; i < 8; i++)
#pragma unroll
                for (int j = 0; j < 4; j++) acc[i][j] = fmaf(a[i], bb[j], acc[i][j]);
        }
        __syncthreads();
    }

    if (MODE == 0) {
        float4 bv = *(const float4*)&bias[bn + tx * 4];
#pragma unroll
        for (int i = 0; i < 8; i++) {
            int r = bm + ty * 8 + i;
            float4 o;
            o.x = acc[i][0] + bv.x;
            o.y = acc[i][1] + bv.y;
            o.z = acc[i][2] + bv.z;
            o.w = acc[i][3] + bv.w;
            *(float4*)&Cout[(size_t)r * N + bn + tx * 4] = o;
        }
    } else {
        float s0   = scales[0];
        float invt = 1.0f / fmaxf(temp[0], TEMP_MIN);
        float m2s  = 2.0f * s0;
        float4 cv = *(const float4*)&cn[bn + tx * 4];
        float cna[4] = {cv.x, cv.y, cv.z, cv.w};
#pragma unroll
        for (int i = 0; i < 8; i++) {
            int r = bm + ty * 8 + i;
            float rnv = rn[r];
            float4 o;
            o.x = -(rnv + cna[0] - m2s * acc[i][0]) * invt;
            o.y = -(rnv + cna[1] - m2s * acc[i][1]) * invt;
            o.z = -(rnv + cna[2] - m2s * acc[i][2]) * invt;
            o.w = -(rnv + cna[3] - m2s * acc[i][3]) * invt;
            *(float4*)&Cout[(size_t)r * (NL * NK) + bn + tx * 4] = o;
        }
    }
}

// ---------------------------------------------------------------------------
// Levels 1..3 logits: broadcast of -||cb_{l,k}||^2 / temp across batch.
// ---------------------------------------------------------------------------
__global__ void __launch_bounds__(256) fill_kernel(const float* __restrict__ temp,
                                                   float* __restrict__ out) {
    float invt = 1.0f / fmaxf(temp[0], TEMP_MIN);
    size_t idx = ((size_t)blockIdx.x * blockDim.x + threadIdx.x) * 4;
    const size_t span = (size_t)3 * NK;  // 6144 per row (levels 1..3)
    size_t total = (size_t)NB * span;
    if (idx >= total) return;
    size_t b = idx / span;
    int i = (int)(idx - b * span);  // multiple of 4, i+3 < 6144
    float4 v;
    v.x = -g_cn[NK + i + 0] * invt;
    v.y = -g_cn[NK + i + 1] * invt;
    v.z = -g_cn[NK + i + 2] * invt;
    v.w = -g_cn[NK + i + 3] * invt;
    *(float4*)&out[b * (size_t)(NL * NK) + NK + i] = v;
}

// ---------------------------------------------------------------------------
extern "C" void kernel_launch(void* const* d_in, const int* in_sizes, int n_in,
                              void* d_out, int out_size) {
    const float* features = (const float*)d_in[0];
    const float* Wp       = (const float*)d_in[1];
    const float* bproj    = (const float*)d_in[2];
    const float* lng      = (const float*)d_in[3];
    const float* lnb      = (const float*)d_in[4];
    const float* cbs      = (const float*)d_in[5];
    const float* scales   = (const float*)d_in[6];
    const float* temp     = (const float*)d_in[7];
    float* out = (float*)d_out;
    float* out_q = out + (size_t)NB * NL * NK;

    float *dy, *dx, *drn, *dcn;
    cudaGetSymbolAddress((void**)&dy, g_y);
    cudaGetSymbolAddress((void**)&dx, g_x);
    cudaGetSymbolAddress((void**)&drn, g_rn);
    cudaGetSymbolAddress((void**)&dcn, g_cn);

    // 1. proj GEMM: g_y = features @ W^T + b
    {
        dim3 grid(ND / 64, NB / 128);
        gemm_nt<0><<<grid, 256>>>(features, Wp, dy, ND, ND, bproj, nullptr, nullptr,
                                  nullptr, nullptr);
    }
    // 2. fused LN + ReLU + LN2 + rownorm
    ln_kernel<<<NB, 256>>>(lng, lnb, scales, out_q);
    // 3. codebook norms
    cbnorm_kernel<<<(NL * NK) / 8, 256>>>(cbs, dcn);
    // 4. level-0 logits GEMM with fused distance epilogue
    {
        dim3 grid(NK / 64, NB / 128);
        gemm_nt<1><<<grid, 256>>>(dx, cbs, out, NK, ND, nullptr, drn, dcn, scales, temp);
    }
    // 5. levels 1..3 broadcast fill
    {
        size_t total4 = (size_t)NB * 3 * NK / 4;
        int blocks = (int)((total4 + 255) / 256);
        fill_kernel<<<blocks, 256>>>(temp, out);
    }
}

// round 3
// speedup vs baseline: 1.4022x; 1.4022x over previous
#include <cuda_runtime.h>
#include <cuda_bf16.h>
#include <cstdint>

#define NB 8192
#define ND 512
#define NK 2048
#define NL 4
#define EPSN 1e-5f
#define TEMP_MIN 0.01f

// GEMM tiling
#define BM 128
#define BN 128
#define BK 32
// smem: 4 arrays (Ahi,Alo,Bhi,Blo) x [128 rows][40 bf16] x 2 buffers
static constexpr int ROWB = 80;                    // bytes per row (40 bf16)
static constexpr int ARRB = BM * ROWB;             // 10240 B
static constexpr int BUFB = 4 * ARRB;              // 40960 B
static constexpr int SMEM_TOTAL = 2 * BUFB;        // 81920 B

// Scratch (no allocations allowed)
static __device__ float g_y[NB * ND];   // proj output pre-LN
static __device__ float g_x[NB * ND];   // relu(LN(...)) output
static __device__ float g_rn[NB];       // ||s0 * x_b||^2
static __device__ float g_cn[NL * NK];  // ||cb[l][k]||^2

// ---------------------------------------------------------------------------
__device__ __forceinline__ uint32_t smem_u32(const void* p) {
    uint32_t a;
    asm("{ .reg .u64 t; cvta.to.shared.u64 t, %1; cvt.u32.u64 %0, t; }" : "=r"(a) : "l"(p));
    return a;
}

__device__ __forceinline__ void ldm_x4(uint32_t* r, uint32_t addr) {
    asm volatile("ldmatrix.sync.aligned.m8n8.x4.shared.b16 {%0,%1,%2,%3}, [%4];"
                 : "=r"(r[0]), "=r"(r[1]), "=r"(r[2]), "=r"(r[3]) : "r"(addr));
}

__device__ __forceinline__ void mma16816(float* c, const uint32_t* a, const uint32_t* b) {
    asm volatile(
        "mma.sync.aligned.m16n8k16.row.col.f32.bf16.bf16.f32 "
        "{%0,%1,%2,%3}, {%4,%5,%6,%7}, {%8,%9}, {%0,%1,%2,%3};"
        : "+f"(c[0]), "+f"(c[1]), "+f"(c[2]), "+f"(c[3])
        : "r"(a[0]), "r"(a[1]), "r"(a[2]), "r"(a[3]), "r"(b[0]), "r"(b[1]));
}

// fp32 float4 -> bf16 hi (uint2) + bf16 lo (uint2)
__device__ __forceinline__ void cvt4(float4 v, uint2& h, uint2& l) {
    __nv_bfloat162 h0 = __floats2bfloat162_rn(v.x, v.y);
    __nv_bfloat162 h1 = __floats2bfloat162_rn(v.z, v.w);
    float lx = v.x - __bfloat162float(h0.x);
    float ly = v.y - __bfloat162float(h0.y);
    float lz = v.z - __bfloat162float(h1.x);
    float lw = v.w - __bfloat162float(h1.y);
    __nv_bfloat162 l0 = __floats2bfloat162_rn(lx, ly);
    __nv_bfloat162 l1 = __floats2bfloat162_rn(lz, lw);
    h.x = *(uint32_t*)&h0; h.y = *(uint32_t*)&h1;
    l.x = *(uint32_t*)&l0; l.y = *(uint32_t*)&l1;
}

// ---------------------------------------------------------------------------
// Split-bf16 tensor-core GEMM: C[M,N] = A[M,512] * B[N,512]^T
// MODE 0: += bias (proj).  MODE 1: logits epilogue.
// ---------------------------------------------------------------------------
template <int MODE>
__global__ void __launch_bounds__(256) gemm_mma(const float* __restrict__ A,
                                               const float* __restrict__ B,
                                               float* __restrict__ C, int ldc,
                                               const float* __restrict__ bias,
                                               const float* __restrict__ rn,
                                               const float* __restrict__ cn,
                                               const float* __restrict__ scales,
                                               const float* __restrict__ temp) {
    extern __shared__ char sm_[];
    const int tid = threadIdx.x;
    const int wid = tid >> 5, lane = tid & 31;
    const int bm = blockIdx.y * BM, bn = blockIdx.x * BN;
    const int wm = (wid & 1) * 64;   // warp row offset within tile
    const int wn = (wid >> 1) * 32;  // warp col offset within tile

    const uint32_t sbase = smem_u32(sm_);

    const int r0 = tid >> 3;        // 0..31 staging row
    const int c4 = (tid & 7) * 4;   // staging col (floats)
    float4 areg[4], breg[4];

    float acc[4][4][4];
#pragma unroll
    for (int mi = 0; mi < 4; mi++)
#pragma unroll
        for (int ni = 0; ni < 4; ni++)
#pragma unroll
            for (int j = 0; j < 4; j++) acc[mi][ni][j] = 0.f;

    // preload chunk 0
#pragma unroll
    for (int i = 0; i < 4; i++) {
        areg[i] = *(const float4*)&A[(size_t)(bm + r0 + 32 * i) * ND + c4];
        breg[i] = *(const float4*)&B[(size_t)(bn + r0 + 32 * i) * ND + c4];
    }

    const int NCH = ND / BK;  // 16
    for (int kc = 0; kc < NCH; kc++) {
        const int buf = kc & 1;
        char* ah = sm_ + buf * BUFB;
        char* al = ah + ARRB;
        char* bh = al + ARRB;
        char* bl = bh + ARRB;
        // store staged regs -> smem (hi/lo split)
        {
            const int off0 = r0 * ROWB + (tid & 7) * 8;
#pragma unroll
            for (int i = 0; i < 4; i++) {
                int off = off0 + i * 32 * ROWB;
                uint2 h, l;
                cvt4(areg[i], h, l);
                *(uint2*)(ah + off) = h; *(uint2*)(al + off) = l;
                cvt4(breg[i], h, l);
                *(uint2*)(bh + off) = h; *(uint2*)(bl + off) = l;
            }
        }
        __syncthreads();
        // prefetch next chunk
        if (kc + 1 < NCH) {
            int kbase = (kc + 1) * BK + c4;
#pragma unroll
            for (int i = 0; i < 4; i++) {
                areg[i] = *(const float4*)&A[(size_t)(bm + r0 + 32 * i) * ND + kbase];
                breg[i] = *(const float4*)&B[(size_t)(bn + r0 + 32 * i) * ND + kbase];
            }
        }
        // MMA over this chunk: 2 k16 steps
        const uint32_t ahb = sbase + buf * BUFB;
        const uint32_t alb = ahb + ARRB;
        const uint32_t bhb = alb + ARRB;
        const uint32_t blb = bhb + ARRB;
        const int arow = lane & 15, akoff = (lane >> 4) * 8;
        const int brow = ((lane >> 4) << 3) + (lane & 7);
        const int bkoff = ((lane >> 3) & 1) * 8;
#pragma unroll
        for (int ks = 0; ks < 2; ks++) {
            const int k0 = ks * 16;
            uint32_t afh[4][4], afl[4][4], bfh[4][2], bfl[4][2];
#pragma unroll
            for (int mi = 0; mi < 4; mi++) {
                uint32_t off = (uint32_t)(wm + mi * 16 + arow) * ROWB + (k0 + akoff) * 2;
                ldm_x4(afh[mi], ahb + off);
                ldm_x4(afl[mi], alb + off);
            }
            {
                uint32_t off = (uint32_t)(wn + brow) * ROWB + (k0 + bkoff) * 2;
                uint32_t t4[4];
                ldm_x4(t4, bhb + off);
                bfh[0][0] = t4[0]; bfh[0][1] = t4[1]; bfh[1][0] = t4[2]; bfh[1][1] = t4[3];
                ldm_x4(t4, bhb + off + 16 * ROWB);
                bfh[2][0] = t4[0]; bfh[2][1] = t4[1]; bfh[3][0] = t4[2]; bfh[3][1] = t4[3];
                ldm_x4(t4, blb + off);
                bfl[0][0] = t4[0]; bfl[0][1] = t4[1]; bfl[1][0] = t4[2]; bfl[1][1] = t4[3];
                ldm_x4(t4, blb + off + 16 * ROWB);
                bfl[2][0] = t4[0]; bfl[2][1] = t4[1]; bfl[3][0] = t4[2]; bfl[3][1] = t4[3];
            }
#pragma unroll
            for (int mi = 0; mi < 4; mi++)
#pragma unroll
                for (int ni = 0; ni < 4; ni++) {
                    mma16816(acc[mi][ni], afh[mi], bfh[ni]);
                    mma16816(acc[mi][ni], afh[mi], bfl[ni]);
                    mma16816(acc[mi][ni], afl[mi], bfh[ni]);
                }
        }
        __syncthreads();
    }

    // Epilogue (fused)
    const int gid = lane >> 2, t4i = lane & 3;
    float s0 = 0.f, invt = 0.f;
    if (MODE == 1) {
        s0 = scales[0];
        invt = 1.0f / fmaxf(temp[0], TEMP_MIN);
    }
#pragma unroll
    for (int mi = 0; mi < 4; mi++) {
        int r = bm + wm + mi * 16 + gid;
#pragma unroll
        for (int ni = 0; ni < 4; ni++) {
            int c = bn + wn + ni * 8 + t4i * 2;
            float* a4 = acc[mi][ni];
            if (MODE == 0) {
                float b0 = bias[c], b1 = bias[c + 1];
                float2 o0 = make_float2(a4[0] + b0, a4[1] + b1);
                float2 o1 = make_float2(a4[2] + b0, a4[3] + b1);
                *(float2*)&C[(size_t)r * ldc + c] = o0;
                *(float2*)&C[(size_t)(r + 8) * ldc + c] = o1;
            } else {
                float m2s = 2.0f * s0;
                float cv0 = cn[c], cv1 = cn[c + 1];
                float rv0 = rn[r], rv1 = rn[r + 8];
                float2 o0, o1;
                o0.x = -(rv0 + cv0 - m2s * a4[0]) * invt;
                o0.y = -(rv0 + cv1 - m2s * a4[1]) * invt;
                o1.x = -(rv1 + cv0 - m2s * a4[2]) * invt;
                o1.y = -(rv1 + cv1 - m2s * a4[3]) * invt;
                *(float2*)&C[(size_t)r * ldc + c] = o0;
                *(float2*)&C[(size_t)(r + 8) * ldc + c] = o1;
            }
        }
    }
}

// ---------------------------------------------------------------------------
__device__ __forceinline__ void block_reduce2(float& a, float& b, float* sbuf) {
#pragma unroll
    for (int o = 16; o > 0; o >>= 1) {
        a += __shfl_xor_sync(0xffffffffu, a, o);
        b += __shfl_xor_sync(0xffffffffu, b, o);
    }
    int w = threadIdx.x >> 5;
    if ((threadIdx.x & 31) == 0) { sbuf[w] = a; sbuf[8 + w] = b; }
    __syncthreads();
    float ta = 0.f, tb = 0.f;
#pragma unroll
    for (int i = 0; i < 8; i++) { ta += sbuf[i]; tb += sbuf[8 + i]; }
    a = ta; b = tb;
    __syncthreads();
}

__global__ void __launch_bounds__(256) cbnorm_kernel(const float* __restrict__ cb,
                                                     float* __restrict__ cn) {
    int row = blockIdx.x * 8 + (threadIdx.x >> 5);
    int lane = threadIdx.x & 31;
    const float* p = cb + (size_t)row * ND;
    float s = 0.f;
#pragma unroll
    for (int i = 0; i < 4; i++) {
        float4 v = *(const float4*)&p[(lane + i * 32) * 4];
        s += v.x * v.x + v.y * v.y + v.z * v.z + v.w * v.w;
    }
#pragma unroll
    for (int o = 16; o > 0; o >>= 1) s += __shfl_xor_sync(0xffffffffu, s, o);
    if (lane == 0) cn[row] = s;
}

__global__ void __launch_bounds__(256) ln_kernel(const float* __restrict__ lng,
                                                 const float* __restrict__ lnb,
                                                 const float* __restrict__ scales,
                                                 float* __restrict__ q_out) {
    __shared__ float red[16];
    int b = blockIdx.x;
    int t = threadIdx.x;
    const float* y = g_y + (size_t)b * ND;
    float2 v = *(const float2*)&y[t * 2];

    float s = v.x + v.y;
    float s2 = v.x * v.x + v.y * v.y;
    block_reduce2(s, s2, red);
    float mu = s * (1.0f / ND);
    float var = s2 * (1.0f / ND) - mu * mu;
    float rstd = rsqrtf(var + EPSN);

    float g0 = lng[t * 2], g1 = lng[t * 2 + 1];
    float b0 = lnb[t * 2], b1 = lnb[t * 2 + 1];
    float x0 = fmaxf((v.x - mu) * rstd * g0 + b0, 0.0f);
    float x1 = fmaxf((v.y - mu) * rstd * g1 + b1, 0.0f);
    float2 xo; xo.x = x0; xo.y = x1;
    *(float2*)&g_x[(size_t)b * ND + t * 2] = xo;

    float s0 = scales[0];
    float v0 = s0 * x0, v1 = s0 * x1;
    float ss = v0 + v1, ss2 = v0 * v0 + v1 * v1;
    block_reduce2(ss, ss2, red);
    if (t == 0) g_rn[b] = ss2;
    float mu2 = ss * (1.0f / ND);
    float var2 = ss2 * (1.0f / ND) - mu2 * mu2;
    float rstd2 = rsqrtf(var2 + EPSN);
    float2 qo;
    qo.x = (v0 - mu2) * rstd2;
    qo.y = (v1 - mu2) * rstd2;
    *(float2*)&q_out[(size_t)b * ND + t * 2] = qo;
}

__global__ void __launch_bounds__(256) fill_kernel(const float* __restrict__ temp,
                                                   float* __restrict__ out) {
    float invt = 1.0f / fmaxf(temp[0], TEMP_MIN);
    size_t idx = ((size_t)blockIdx.x * blockDim.x + threadIdx.x) * 4;
    const size_t span = (size_t)3 * NK;
    size_t total = (size_t)NB * span;
    if (idx >= total) return;
    size_t b = idx / span;
    int i = (int)(idx - b * span);
    float4 v;
    v.x = -g_cn[NK + i + 0] * invt;
    v.y = -g_cn[NK + i + 1] * invt;
    v.z = -g_cn[NK + i + 2] * invt;
    v.w = -g_cn[NK + i + 3] * invt;
    *(float4*)&out[b * (size_t)(NL * NK) + NK + i] = v;
}

// ---------------------------------------------------------------------------
extern "C" void kernel_launch(void* const* d_in, const int* in_sizes, int n_in,
                              void* d_out, int out_size) {
    const float* features = (const float*)d_in[0];
    const float* Wp       = (const float*)d_in[1];
    const float* bproj    = (const float*)d_in[2];
    const float* lng      = (const float*)d_in[3];
    const float* lnb      = (const float*)d_in[4];
    const float* cbs      = (const float*)d_in[5];
    const float* scales   = (const float*)d_in[6];
    const float* temp     = (const float*)d_in[7];
    float* out = (float*)d_out;
    float* out_q = out + (size_t)NB * NL * NK;

    float *dy, *dx, *drn, *dcn;
    cudaGetSymbolAddress((void**)&dy, g_y);
    cudaGetSymbolAddress((void**)&dx, g_x);
    cudaGetSymbolAddress((void**)&drn, g_rn);
    cudaGetSymbolAddress((void**)&dcn, g_cn);

    cudaFuncSetAttribute(gemm_mma<0>, cudaFuncAttributeMaxDynamicSharedMemorySize, SMEM_TOTAL);
    cudaFuncSetAttribute(gemm_mma<1>, cudaFuncAttributeMaxDynamicSharedMemorySize, SMEM_TOTAL);

    // 1. proj GEMM: g_y = features @ W^T + b
    {
        dim3 grid(ND / BN, NB / BM);
        gemm_mma<0><<<grid, 256, SMEM_TOTAL>>>(features, Wp, dy, ND, bproj,
                                               nullptr, nullptr, nullptr, nullptr);
    }
    // 2. fused LN + ReLU + LN2 + rownorm
    ln_kernel<<<NB, 256>>>(lng, lnb, scales, out_q);
    // 3. codebook norms
    cbnorm_kernel<<<(NL * NK) / 8, 256>>>(cbs, dcn);
    // 4. level-0 logits GEMM with fused distance epilogue
    {
        dim3 grid(NK / BN, NB / BM);
        gemm_mma<1><<<grid, 256, SMEM_TOTAL>>>(dx, cbs, out, NL * NK, nullptr,
                                               drn, dcn, scales, temp);
    }
    // 5. levels 1..3 broadcast fill
    {
        size_t total4 = (size_t)NB * 3 * NK / 4;
        int blocks = (int)((total4 + 255) / 256);
        fill_kernel<<<blocks, 256>>>(temp, out);
    }
}

// round 4
// speedup vs baseline: 2.2841x; 1.6289x over previous
#include <cuda_runtime.h>
#include <cuda_bf16.h>
#include <cstdint>

#define NB 8192
#define ND 512
#define NK 2048
#define NL 4
#define EPSN 1e-5f
#define TEMP_MIN 0.01f

// GEMM tiling: 512 threads, tile 128x256, warp tile 64x32, BK=32
#define BM 128
#define BN 256
#define BK 32
static constexpr int ROWB = 80;                      // bytes per smem row (40 bf16)
static constexpr int ARR_A = BM * ROWB;              // 10240
static constexpr int ARR_B = BN * ROWB;              // 20480
static constexpr int BUFB = 2 * ARR_A + 2 * ARR_B;   // 61440 (Ahi,Alo,Bhi,Blo)
static constexpr int SMEM_TOTAL = 2 * BUFB;          // 122880

// Scratch
static __device__ float g_y[NB * ND];
static __device__ float g_x[NB * ND];
static __device__ float g_rn[NB];
static __device__ float g_cn[NL * NK];

// ---------------------------------------------------------------------------
__device__ __forceinline__ uint32_t smem_u32(const void* p) {
    uint32_t a;
    asm("{ .reg .u64 t; cvta.to.shared.u64 t, %1; cvt.u32.u64 %0, t; }" : "=r"(a) : "l"(p));
    return a;
}

__device__ __forceinline__ void ldm_x4(uint32_t* r, uint32_t addr) {
    asm volatile("ldmatrix.sync.aligned.m8n8.x4.shared.b16 {%0,%1,%2,%3}, [%4];"
                 : "=r"(r[0]), "=r"(r[1]), "=r"(r[2]), "=r"(r[3]) : "r"(addr));
}

__device__ __forceinline__ void mma16816(float* c, const uint32_t* a, const uint32_t* b) {
    asm volatile(
        "mma.sync.aligned.m16n8k16.row.col.f32.bf16.bf16.f32 "
        "{%0,%1,%2,%3}, {%4,%5,%6,%7}, {%8,%9}, {%0,%1,%2,%3};"
        : "+f"(c[0]), "+f"(c[1]), "+f"(c[2]), "+f"(c[3])
        : "r"(a[0]), "r"(a[1]), "r"(a[2]), "r"(a[3]), "r"(b[0]), "r"(b[1]));
}

__device__ __forceinline__ void cvt4(float4 v, uint2& h, uint2& l) {
    __nv_bfloat162 h0 = __floats2bfloat162_rn(v.x, v.y);
    __nv_bfloat162 h1 = __floats2bfloat162_rn(v.z, v.w);
    float lx = v.x - __bfloat162float(h0.x);
    float ly = v.y - __bfloat162float(h0.y);
    float lz = v.z - __bfloat162float(h1.x);
    float lw = v.w - __bfloat162float(h1.y);
    __nv_bfloat162 l0 = __floats2bfloat162_rn(lx, ly);
    __nv_bfloat162 l1 = __floats2bfloat162_rn(lz, lw);
    h.x = *(uint32_t*)&h0; h.y = *(uint32_t*)&h1;
    l.x = *(uint32_t*)&l0; l.y = *(uint32_t*)&l1;
}

// ---------------------------------------------------------------------------
// Split-bf16 tensor GEMM: C[M,N] = A[M,512]*B[N,512]^T
// MODE 0: +bias (proj). MODE 1: logits epilogue + fused level1-3 fill.
// ---------------------------------------------------------------------------
template <int MODE>
__global__ void __launch_bounds__(512) gemm_mma(const float* __restrict__ A,
                                               const float* __restrict__ B,
                                               float* __restrict__ C, int ldc,
                                               const float* __restrict__ bias,
                                               const float* __restrict__ rn,
                                               const float* __restrict__ cn,
                                               const float* __restrict__ scales,
                                               const float* __restrict__ temp) {
    extern __shared__ char sm_[];
    const int tid = threadIdx.x;
    const int wid = tid >> 5, lane = tid & 31;
    const int bm = blockIdx.y * BM, bn = blockIdx.x * BN;
    const int wm = (wid & 1) * 64;
    const int wn = (wid >> 1) * 32;  // 0..224
    const uint32_t sbase = smem_u32(sm_);

    float acc[4][4][4];
#pragma unroll
    for (int mi = 0; mi < 4; mi++)
#pragma unroll
        for (int ni = 0; ni < 4; ni++)
#pragma unroll
            for (int j = 0; j < 4; j++) acc[mi][ni][j] = 0.f;

    // Staging: A = 1024 float4 (2/thread), B = 2048 float4 (4/thread)
    float4 areg[2], breg[4];
#pragma unroll
    for (int i = 0; i < 2; i++) {
        int idx = tid + i * 512;
        areg[i] = *(const float4*)&A[(size_t)(bm + (idx >> 3)) * ND + (idx & 7) * 4];
    }
#pragma unroll
    for (int j = 0; j < 4; j++) {
        int idx = tid + j * 512;
        breg[j] = *(const float4*)&B[(size_t)(bn + (idx >> 3)) * ND + (idx & 7) * 4];
    }

    const int NCH = ND / BK;  // 16
    for (int kc = 0; kc < NCH; kc++) {
        const int buf = kc & 1;
        char* ah = sm_ + buf * BUFB;
        char* al = ah + ARR_A;
        char* bh = al + ARR_A;
        char* bl = bh + ARR_B;
        // store staged regs -> smem (hi/lo split)
#pragma unroll
        for (int i = 0; i < 2; i++) {
            int idx = tid + i * 512;
            int off = (idx >> 3) * ROWB + (idx & 7) * 8;
            uint2 h, l;
            cvt4(areg[i], h, l);
            *(uint2*)(ah + off) = h; *(uint2*)(al + off) = l;
        }
#pragma unroll
        for (int j = 0; j < 4; j++) {
            int idx = tid + j * 512;
            int off = (idx >> 3) * ROWB + (idx & 7) * 8;
            uint2 h, l;
            cvt4(breg[j], h, l);
            *(uint2*)(bh + off) = h; *(uint2*)(bl + off) = l;
        }
        __syncthreads();
        // prefetch next chunk
        if (kc + 1 < NCH) {
            int kb = (kc + 1) * BK;
#pragma unroll
            for (int i = 0; i < 2; i++) {
                int idx = tid + i * 512;
                areg[i] = *(const float4*)&A[(size_t)(bm + (idx >> 3)) * ND + kb + (idx & 7) * 4];
            }
#pragma unroll
            for (int j = 0; j < 4; j++) {
                int idx = tid + j * 512;
                breg[j] = *(const float4*)&B[(size_t)(bn + (idx >> 3)) * ND + kb + (idx & 7) * 4];
            }
        }
        // MMA: 2 k16 steps
        const uint32_t ahb = sbase + buf * BUFB;
        const uint32_t alb = ahb + ARR_A;
        const uint32_t bhb = alb + ARR_A;
        const uint32_t blb = bhb + ARR_B;
        const int arow = lane & 15, akoff = (lane >> 4) * 8;
        const int brow = ((lane >> 4) << 3) + (lane & 7);
        const int bkoff = ((lane >> 3) & 1) * 8;
#pragma unroll
        for (int ks = 0; ks < 2; ks++) {
            const int k0 = ks * 16;
            uint32_t bfh[4][2], bfl[4][2];
            {
                uint32_t off = (uint32_t)(wn + brow) * ROWB + (k0 + bkoff) * 2;
                uint32_t t4[4];
                ldm_x4(t4, bhb + off);
                bfh[0][0] = t4[0]; bfh[0][1] = t4[1]; bfh[1][0] = t4[2]; bfh[1][1] = t4[3];
                ldm_x4(t4, bhb + off + 16 * ROWB);
                bfh[2][0] = t4[0]; bfh[2][1] = t4[1]; bfh[3][0] = t4[2]; bfh[3][1] = t4[3];
                ldm_x4(t4, blb + off);
                bfl[0][0] = t4[0]; bfl[0][1] = t4[1]; bfl[1][0] = t4[2]; bfl[1][1] = t4[3];
                ldm_x4(t4, blb + off + 16 * ROWB);
                bfl[2][0] = t4[0]; bfl[2][1] = t4[1]; bfl[3][0] = t4[2]; bfl[3][1] = t4[3];
            }
#pragma unroll
            for (int mi = 0; mi < 4; mi++) {
                uint32_t aoff = (uint32_t)(wm + mi * 16 + arow) * ROWB + (k0 + akoff) * 2;
                uint32_t afh[4];
                ldm_x4(afh, ahb + aoff);
#pragma unroll
                for (int ni = 0; ni < 4; ni++) mma16816(acc[mi][ni], afh, bfh[ni]);
#pragma unroll
                for (int ni = 0; ni < 4; ni++) mma16816(acc[mi][ni], afh, bfl[ni]);
                uint32_t afl[4];
                ldm_x4(afl, alb + aoff);
#pragma unroll
                for (int ni = 0; ni < 4; ni++) mma16816(acc[mi][ni], afl, bfh[ni]);
            }
        }
        __syncthreads();
    }

    // Epilogue
    const int gid = lane >> 2, t4i = lane & 3;
    float s0 = 0.f, invt = 0.f;
    if (MODE == 1) {
        s0 = scales[0];
        invt = 1.0f / fmaxf(temp[0], TEMP_MIN);
    }

    // Precompute fill values (levels 1..3 slice for this bx) into smem
    float* sval = (float*)sm_;
    if (MODE == 1) {
        int cbase = NK + blockIdx.x * 768;
        for (int i = tid; i < 768; i += 512) sval[i] = -cn[cbase + i] * invt;
        __syncthreads();
    }

#pragma unroll
    for (int mi = 0; mi < 4; mi++) {
        int r = bm + wm + mi * 16 + gid;
#pragma unroll
        for (int ni = 0; ni < 4; ni++) {
            int c = bn + wn + ni * 8 + t4i * 2;
            float* a4 = acc[mi][ni];
            if (MODE == 0) {
                float b0 = bias[c], b1 = bias[c + 1];
                *(float2*)&C[(size_t)r * ldc + c] = make_float2(a4[0] + b0, a4[1] + b1);
                *(float2*)&C[(size_t)(r + 8) * ldc + c] = make_float2(a4[2] + b0, a4[3] + b1);
            } else {
                float m2s = 2.0f * s0;
                float cv0 = cn[c], cv1 = cn[c + 1];
                float rv0 = rn[r], rv1 = rn[r + 8];
                float2 o0, o1;
                o0.x = -(rv0 + cv0 - m2s * a4[0]) * invt;
                o0.y = -(rv0 + cv1 - m2s * a4[1]) * invt;
                o1.x = -(rv1 + cv0 - m2s * a4[2]) * invt;
                o1.y = -(rv1 + cv1 - m2s * a4[3]) * invt;
                *(float2*)&C[(size_t)r * ldc + c] = o0;
                *(float2*)&C[(size_t)(r + 8) * ldc + c] = o1;
            }
        }
    }

    // Fused fill: this CTA writes its 768-col slice of levels 1..3 for its rows
    if (MODE == 1) {
        int fbase = NK + blockIdx.x * 768;
#pragma unroll
        for (int j = 0; j < 48; j++) {
            int idx = tid + j * 512;         // 24576 float4 per CTA
            int row = idx / 192;
            int cc = (idx - row * 192) * 4;  // 0..764
            float4 v = *(float4*)&sval[cc];
            *(float4*)&C[(size_t)(bm + row) * ldc + fbase + cc] = v;
        }
    }
}

// ---------------------------------------------------------------------------
__device__ __forceinline__ void block_reduce2(float& a, float& b, float* sbuf) {
#pragma unroll
    for (int o = 16; o > 0; o >>= 1) {
        a += __shfl_xor_sync(0xffffffffu, a, o);
        b += __shfl_xor_sync(0xffffffffu, b, o);
    }
    int w = threadIdx.x >> 5;
    if ((threadIdx.x & 31) == 0) { sbuf[w] = a; sbuf[8 + w] = b; }
    __syncthreads();
    float ta = 0.f, tb = 0.f;
#pragma unroll
    for (int i = 0; i < 8; i++) { ta += sbuf[i]; tb += sbuf[8 + i]; }
    a = ta; b = tb;
    __syncthreads();
}

__global__ void __launch_bounds__(256) cbnorm_kernel(const float* __restrict__ cb,
                                                     float* __restrict__ cn) {
    int row = blockIdx.x * 8 + (threadIdx.x >> 5);
    int lane = threadIdx.x & 31;
    const float* p = cb + (size_t)row * ND;
    float s = 0.f;
#pragma unroll
    for (int i = 0; i < 4; i++) {
        float4 v = *(const float4*)&p[(lane + i * 32) * 4];
        s += v.x * v.x + v.y * v.y + v.z * v.z + v.w * v.w;
    }
#pragma unroll
    for (int o = 16; o > 0; o >>= 1) s += __shfl_xor_sync(0xffffffffu, s, o);
    if (lane == 0) cn[row] = s;
}

__global__ void __launch_bounds__(256) ln_kernel(const float* __restrict__ lng,
                                                 const float* __restrict__ lnb,
                                                 const float* __restrict__ scales,
                                                 float* __restrict__ q_out) {
    __shared__ float red[16];
    int b = blockIdx.x;
    int t = threadIdx.x;
    const float* y = g_y + (size_t)b * ND;
    float2 v = *(const float2*)&y[t * 2];

    float s = v.x + v.y;
    float s2 = v.x * v.x + v.y * v.y;
    block_reduce2(s, s2, red);
    float mu = s * (1.0f / ND);
    float var = s2 * (1.0f / ND) - mu * mu;
    float rstd = rsqrtf(var + EPSN);

    float g0 = lng[t * 2], g1 = lng[t * 2 + 1];
    float b0 = lnb[t * 2], b1 = lnb[t * 2 + 1];
    float x0 = fmaxf((v.x - mu) * rstd * g0 + b0, 0.0f);
    float x1 = fmaxf((v.y - mu) * rstd * g1 + b1, 0.0f);
    float2 xo; xo.x = x0; xo.y = x1;
    *(float2*)&g_x[(size_t)b * ND + t * 2] = xo;

    float s0 = scales[0];
    float v0 = s0 * x0, v1 = s0 * x1;
    float ss = v0 + v1, ss2 = v0 * v0 + v1 * v1;
    block_reduce2(ss, ss2, red);
    if (t == 0) g_rn[b] = ss2;
    float mu2 = ss * (1.0f / ND);
    float var2 = ss2 * (1.0f / ND) - mu2 * mu2;
    float rstd2 = rsqrtf(var2 + EPSN);
    float2 qo;
    qo.x = (v0 - mu2) * rstd2;
    qo.y = (v1 - mu2) * rstd2;
    *(float2*)&q_out[(size_t)b * ND + t * 2] = qo;
}

// ---------------------------------------------------------------------------
extern "C" void kernel_launch(void* const* d_in, const int* in_sizes, int n_in,
                              void* d_out, int out_size) {
    const float* features = (const float*)d_in[0];
    const float* Wp       = (const float*)d_in[1];
    const float* bproj    = (const float*)d_in[2];
    const float* lng      = (const float*)d_in[3];
    const float* lnb      = (const float*)d_in[4];
    const float* cbs      = (const float*)d_in[5];
    const float* scales   = (const float*)d_in[6];
    const float* temp     = (const float*)d_in[7];
    float* out = (float*)d_out;
    float* out_q = out + (size_t)NB * NL * NK;

    float *dy, *dx, *drn, *dcn;
    cudaGetSymbolAddress((void**)&dy, g_y);
    cudaGetSymbolAddress((void**)&dx, g_x);
    cudaGetSymbolAddress((void**)&drn, g_rn);
    cudaGetSymbolAddress((void**)&dcn, g_cn);

    cudaFuncSetAttribute(gemm_mma<0>, cudaFuncAttributeMaxDynamicSharedMemorySize, SMEM_TOTAL);
    cudaFuncSetAttribute(gemm_mma<1>, cudaFuncAttributeMaxDynamicSharedMemorySize, SMEM_TOTAL);

    // 1. proj GEMM: g_y = features @ W^T + b
    {
        dim3 grid(ND / BN, NB / BM);
        gemm_mma<0><<<grid, 512, SMEM_TOTAL>>>(features, Wp, dy, ND, bproj,
                                               nullptr, nullptr, nullptr, nullptr);
    }
    // 2. fused LN + ReLU + LN2 + rownorm
    ln_kernel<<<NB, 256>>>(lng, lnb, scales, out_q);
    // 3. codebook norms
    cbnorm_kernel<<<(NL * NK) / 8, 256>>>(cbs, dcn);
    // 4. level-0 logits GEMM + fused distance epilogue + fused level1-3 fill
    {
        dim3 grid(NK / BN, NB / BM);
        gemm_mma<1><<<grid, 512, SMEM_TOTAL>>>(dx, cbs, out, NL * NK, nullptr,
                                               drn, dcn, scales, temp);
    }
}

// round 5
// speedup vs baseline: 2.7192x; 1.1905x over previous
#include <cuda_runtime.h>
#include <cuda_bf16.h>
#include <cstdint>

#define NB 8192
#define ND 512
#define NK 2048
#define NL 4
#define EPSN 1e-5f
#define TEMP_MIN 0.01f

// GEMM: tile 128x128, 256 threads, BK=32, 3-stage cp.async pipeline
#define BM 128
#define BN 128
#define BK 32
static constexpr int STAGE_B = 32768;           // Ah(8K)+Al(8K)+Bh(8K)+Bl(8K)
static constexpr int SMEM_TOTAL = 3 * STAGE_B;  // 98304

// Scratch (static device arrays; no allocations)
static __device__ float g_y[NB * ND];
static __device__ __align__(16) __nv_bfloat16 g_fh[NB * ND];   // features hi
static __device__ __align__(16) __nv_bfloat16 g_fl[NB * ND];   // features lo
static __device__ __align__(16) __nv_bfloat16 g_wh[ND * ND];   // W_proj hi
static __device__ __align__(16) __nv_bfloat16 g_wl[ND * ND];   // W_proj lo
static __device__ __align__(16) __nv_bfloat16 g_xh[NB * ND];   // x hi
static __device__ __align__(16) __nv_bfloat16 g_xl[NB * ND];   // x lo
static __device__ __align__(16) __nv_bfloat16 g_ch[NK * ND];   // codebook0 hi
static __device__ __align__(16) __nv_bfloat16 g_cl[NK * ND];   // codebook0 lo
static __device__ float g_rn[NB];
static __device__ float g_cn[NL * NK];

// ---------------------------------------------------------------------------
__device__ __forceinline__ uint32_t smem_u32(const void* p) {
    uint32_t a;
    asm("{ .reg .u64 t; cvta.to.shared.u64 t, %1; cvt.u32.u64 %0, t; }" : "=r"(a) : "l"(p));
    return a;
}

#define CPA(dst, src) \
    asm volatile("cp.async.cg.shared.global [%0], [%1], 16;" :: "r"(dst), "l"(src) : "memory")
#define CPA_COMMIT() asm volatile("cp.async.commit_group;" ::: "memory")
#define CPA_WAIT(N)  asm volatile("cp.async.wait_group %0;" :: "n"(N) : "memory")

__device__ __forceinline__ void ldm_x4(uint32_t* r, uint32_t addr) {
    asm volatile("ldmatrix.sync.aligned.m8n8.x4.shared.b16 {%0,%1,%2,%3}, [%4];"
                 : "=r"(r[0]), "=r"(r[1]), "=r"(r[2]), "=r"(r[3]) : "r"(addr));
}

__device__ __forceinline__ void mma16816(float* c, const uint32_t* a, const uint32_t* b) {
    asm volatile(
        "mma.sync.aligned.m16n8k16.row.col.f32.bf16.bf16.f32 "
        "{%0,%1,%2,%3}, {%4,%5,%6,%7}, {%8,%9}, {%0,%1,%2,%3};"
        : "+f"(c[0]), "+f"(c[1]), "+f"(c[2]), "+f"(c[3])
        : "r"(a[0]), "r"(a[1]), "r"(a[2]), "r"(a[3]), "r"(b[0]), "r"(b[1]));
}

__device__ __forceinline__ void cvt4(float4 v, uint2& h, uint2& l) {
    __nv_bfloat162 h0 = __floats2bfloat162_rn(v.x, v.y);
    __nv_bfloat162 h1 = __floats2bfloat162_rn(v.z, v.w);
    float lx = v.x - __bfloat162float(h0.x);
    float ly = v.y - __bfloat162float(h0.y);
    float lz = v.z - __bfloat162float(h1.x);
    float lw = v.w - __bfloat162float(h1.y);
    __nv_bfloat162 l0 = __floats2bfloat162_rn(lx, ly);
    __nv_bfloat162 l1 = __floats2bfloat162_rn(lz, lw);
    h.x = *(uint32_t*)&h0; h.y = *(uint32_t*)&h1;
    l.x = *(uint32_t*)&l0; l.y = *(uint32_t*)&l1;
}

// swizzled smem byte offset for (row, 16B-chunk cc) in a 128x64B array
__device__ __forceinline__ uint32_t swz(int row, int cc) {
    return (uint32_t)(row * 64 + ((cc ^ ((row >> 1) & 3)) << 4));
}

// ---------------------------------------------------------------------------
// cp.async stage issue: 8 chunks of 16B per thread (2 rows x 4 arrays)
// ---------------------------------------------------------------------------
__device__ __forceinline__ void issue_stage(uint32_t sb, const char* pAh, const char* pAl,
                                            const char* pBh, const char* pBl,
                                            uint32_t d0, int koff) {
    CPA(sb + d0,                pAh + koff);
    CPA(sb + d0 + 4096,         pAh + koff + 65536);
    CPA(sb + 8192 + d0,         pAl + koff);
    CPA(sb + 8192 + d0 + 4096,  pAl + koff + 65536);
    CPA(sb + 16384 + d0,        pBh + koff);
    CPA(sb + 16384 + d0 + 4096, pBh + koff + 65536);
    CPA(sb + 24576 + d0,        pBl + koff);
    CPA(sb + 24576 + d0 + 4096, pBl + koff + 65536);
    CPA_COMMIT();
}

// ---------------------------------------------------------------------------
// Split-bf16 tensor GEMM on preconverted operands.
// C[M,N] = A[M,512] * B[N,512]^T.  MODE 0: +bias.  MODE 1: logits + fused fill.
// ---------------------------------------------------------------------------
template <int MODE>
__global__ void __launch_bounds__(256, 2) gemm_mma(
    const __nv_bfloat16* __restrict__ Ah_g, const __nv_bfloat16* __restrict__ Al_g,
    const __nv_bfloat16* __restrict__ Bh_g, const __nv_bfloat16* __restrict__ Bl_g,
    float* __restrict__ C, int ldc,
    const float* __restrict__ bias, const float* __restrict__ rn,
    const float* __restrict__ cn, const float* __restrict__ scales,
    const float* __restrict__ temp) {
    extern __shared__ char sm_[];
    const int tid = threadIdx.x;
    const int wid = tid >> 5, lane = tid & 31;
    const int bm = blockIdx.y * BM, bn = blockIdx.x * BN;
    const int wm = (wid & 1) * 64;
    const int wn = (wid >> 1) * 32;
    const uint32_t sbase = smem_u32(sm_);

    // staging addresses (per thread)
    const int r0 = tid >> 2, c0 = tid & 3;
    const uint32_t d0 = swz(r0, c0);
    const char* pAh = (const char*)Ah_g + (size_t)(bm + r0) * 1024 + c0 * 16;
    const char* pAl = (const char*)Al_g + (size_t)(bm + r0) * 1024 + c0 * 16;
    const char* pBh = (const char*)Bh_g + (size_t)(bn + r0) * 1024 + c0 * 16;
    const char* pBl = (const char*)Bl_g + (size_t)(bn + r0) * 1024 + c0 * 16;

    float acc[4][4][4];
#pragma unroll
    for (int mi = 0; mi < 4; mi++)
#pragma unroll
        for (int ni = 0; ni < 4; ni++)
#pragma unroll
            for (int j = 0; j < 4; j++) acc[mi][ni][j] = 0.f;

    // fragment lane mapping
    const int arow = lane & 15, asel = lane >> 4;
    const int brow = ((lane >> 4) << 3) + (lane & 7);
    const int bsel = (lane >> 3) & 1;

    const int NCH = ND / BK;  // 16
    // prologue: stages 0, 1
    issue_stage(sbase, pAh, pAl, pBh, pBl, d0, 0);
    issue_stage(sbase + STAGE_B, pAh, pAl, pBh, pBl, d0, 64);

#pragma unroll 1
    for (int kc = 0; kc < NCH; kc++) {
        if (kc + 2 < NCH) {
            CPA_WAIT(1);
            __syncthreads();
            int s = (kc + 2) % 3;
            issue_stage(sbase + s * STAGE_B, pAh, pAl, pBh, pBl, d0, (kc + 2) * 64);
        } else if (kc + 1 < NCH) {
            CPA_WAIT(1);
            __syncthreads();
        } else {
            CPA_WAIT(0);
            __syncthreads();
        }
        const uint32_t ah = sbase + (kc % 3) * STAGE_B;
        const uint32_t al = ah + 8192;
        const uint32_t bh = ah + 16384;
        const uint32_t bl = ah + 24576;
#pragma unroll
        for (int ks = 0; ks < 2; ks++) {
            const int ccA = ks * 2 + asel;
            const int ccB = ks * 2 + bsel;
            uint32_t bfh[4][2], bfl[4][2];
            {
                int rb = wn + brow;
                uint32_t o1 = swz(rb, ccB), o2 = swz(rb + 16, ccB);
                uint32_t t4[4];
                ldm_x4(t4, bh + o1);
                bfh[0][0] = t4[0]; bfh[0][1] = t4[1]; bfh[1][0] = t4[2]; bfh[1][1] = t4[3];
                ldm_x4(t4, bh + o2);
                bfh[2][0] = t4[0]; bfh[2][1] = t4[1]; bfh[3][0] = t4[2]; bfh[3][1] = t4[3];
                ldm_x4(t4, bl + o1);
                bfl[0][0] = t4[0]; bfl[0][1] = t4[1]; bfl[1][0] = t4[2]; bfl[1][1] = t4[3];
                ldm_x4(t4, bl + o2);
                bfl[2][0] = t4[0]; bfl[2][1] = t4[1]; bfl[3][0] = t4[2]; bfl[3][1] = t4[3];
            }
#pragma unroll
            for (int mi = 0; mi < 4; mi++) {
                int ra = wm + mi * 16 + arow;
                uint32_t ao = swz(ra, ccA);
                uint32_t afh[4];
                ldm_x4(afh, ah + ao);
#pragma unroll
                for (int ni = 0; ni < 4; ni++) mma16816(acc[mi][ni], afh, bfh[ni]);
#pragma unroll
                for (int ni = 0; ni < 4; ni++) mma16816(acc[mi][ni], afh, bfl[ni]);
                uint32_t afl[4];
                ldm_x4(afl, al + ao);
#pragma unroll
                for (int ni = 0; ni < 4; ni++) mma16816(acc[mi][ni], afl, bfh[ni]);
            }
        }
    }
    __syncthreads();

    // Epilogue
    const int gid = lane >> 2, t4i = lane & 3;
    float s0 = 0.f, invt = 0.f;
    if (MODE == 1) {
        s0 = scales[0];
        invt = 1.0f / fmaxf(temp[0], TEMP_MIN);
    }

    float* sval = (float*)sm_;
    if (MODE == 1) {
        int cbase = NK + blockIdx.x * 384;  // 6144 / 16 tiles = 384 cols per bx
        for (int i = tid; i < 384; i += 256) sval[i] = -cn[cbase + i] * invt;
        __syncthreads();
    }

#pragma unroll
    for (int mi = 0; mi < 4; mi++) {
        int r = bm + wm + mi * 16 + gid;
#pragma unroll
        for (int ni = 0; ni < 4; ni++) {
            int c = bn + wn + ni * 8 + t4i * 2;
            float* a4 = acc[mi][ni];
            if (MODE == 0) {
                float b0 = bias[c], b1 = bias[c + 1];
                *(float2*)&C[(size_t)r * ldc + c] = make_float2(a4[0] + b0, a4[1] + b1);
                *(float2*)&C[(size_t)(r + 8) * ldc + c] = make_float2(a4[2] + b0, a4[3] + b1);
            } else {
                float m2s = 2.0f * s0;
                float cv0 = cn[c], cv1 = cn[c + 1];
                float rv0 = rn[r], rv1 = rn[r + 8];
                float2 o0, o1;
                o0.x = -(rv0 + cv0 - m2s * a4[0]) * invt;
                o0.y = -(rv0 + cv1 - m2s * a4[1]) * invt;
                o1.x = -(rv1 + cv0 - m2s * a4[2]) * invt;
                o1.y = -(rv1 + cv1 - m2s * a4[3]) * invt;
                *(float2*)&C[(size_t)r * ldc + c] = o0;
                *(float2*)&C[(size_t)(r + 8) * ldc + c] = o1;
            }
        }
    }

    // Fused levels 1..3 fill: 128 rows x 384 cols per CTA
    if (MODE == 1) {
        int fbase = NK + blockIdx.x * 384;
#pragma unroll
        for (int j = 0; j < 48; j++) {
            int idx = tid + j * 256;  // 12288 float4 per CTA
            int row = idx / 96;
            int cc = (idx - row * 96) * 4;
            float4 v = *(float4*)&sval[cc];
            *(float4*)&C[(size_t)(bm + row) * ldc + fbase + cc] = v;
        }
    }
}

// ---------------------------------------------------------------------------
// fp32 -> bf16 hi/lo converter (elementwise, float4 per thread)
// ---------------------------------------------------------------------------
__global__ void __launch_bounds__(256) conv_kernel(const float* __restrict__ src,
                                                   __nv_bfloat16* __restrict__ h,
                                                   __nv_bfloat16* __restrict__ l) {
    int idx = blockIdx.x * 256 + threadIdx.x;
    float4 v = ((const float4*)src)[idx];
    uint2 hh, ll;
    cvt4(v, hh, ll);
    ((uint2*)h)[idx] = hh;
    ((uint2*)l)[idx] = ll;
}

// ---------------------------------------------------------------------------
__device__ __forceinline__ void block_reduce2(float& a, float& b, float* sbuf) {
#pragma unroll
    for (int o = 16; o > 0; o >>= 1) {
        a += __shfl_xor_sync(0xffffffffu, a, o);
        b += __shfl_xor_sync(0xffffffffu, b, o);
    }
    int w = threadIdx.x >> 5;
    if ((threadIdx.x & 31) == 0) { sbuf[w] = a; sbuf[8 + w] = b; }
    __syncthreads();
    float ta = 0.f, tb = 0.f;
#pragma unroll
    for (int i = 0; i < 8; i++) { ta += sbuf[i]; tb += sbuf[8 + i]; }
    a = ta; b = tb;
    __syncthreads();
}

// Codebook norms + level-0 hi/lo conversion
__global__ void __launch_bounds__(256) cbnorm_kernel(const float* __restrict__ cb,
                                                     float* __restrict__ cn) {
    int row = blockIdx.x * 8 + (threadIdx.x >> 5);
    int lane = threadIdx.x & 31;
    const float* p = cb + (size_t)row * ND;
    float s = 0.f;
#pragma unroll
    for (int i = 0; i < 4; i++) {
        int off = (lane + i * 32) * 4;
        float4 v = *(const float4*)&p[off];
        s += v.x * v.x + v.y * v.y + v.z * v.z + v.w * v.w;
        if (row < NK) {
            uint2 hh, ll;
            cvt4(v, hh, ll);
            *(uint2*)&g_ch[(size_t)row * ND + off] = hh;
            *(uint2*)&g_cl[(size_t)row * ND + off] = ll;
        }
    }
#pragma unroll
    for (int o = 16; o > 0; o >>= 1) s += __shfl_xor_sync(0xffffffffu, s, o);
    if (lane == 0) cn[row] = s;
}

// Fused LN(affine)+ReLU -> x hi/lo bf16, second LN (no affine), row norm
__global__ void __launch_bounds__(256) ln_kernel(const float* __restrict__ lng,
                                                 const float* __restrict__ lnb,
                                                 const float* __restrict__ scales,
                                                 float* __restrict__ q_out) {
    __shared__ float red[16];
    int b = blockIdx.x;
    int t = threadIdx.x;
    const float* y = g_y + (size_t)b * ND;
    float2 v = *(const float2*)&y[t * 2];

    float s = v.x + v.y;
    float s2 = v.x * v.x + v.y * v.y;
    block_reduce2(s, s2, red);
    float mu = s * (1.0f / ND);
    float var = s2 * (1.0f / ND) - mu * mu;
    float rstd = rsqrtf(var + EPSN);

    float g0 = lng[t * 2], g1 = lng[t * 2 + 1];
    float b0 = lnb[t * 2], b1 = lnb[t * 2 + 1];
    float x0 = fmaxf((v.x - mu) * rstd * g0 + b0, 0.0f);
    float x1 = fmaxf((v.y - mu) * rstd * g1 + b1, 0.0f);

    __nv_bfloat162 hp = __floats2bfloat162_rn(x0, x1);
    float l0 = x0 - __bfloat162float(hp.x);
    float l1 = x1 - __bfloat162float(hp.y);
    __nv_bfloat162 lp = __floats2bfloat162_rn(l0, l1);
    ((__nv_bfloat162*)g_xh)[b * 256 + t] = hp;
    ((__nv_bfloat162*)g_xl)[b * 256 + t] = lp;

    float s0 = scales[0];
    float v0 = s0 * x0, v1 = s0 * x1;
    float ss = v0 + v1, ss2 = v0 * v0 + v1 * v1;
    block_reduce2(ss, ss2, red);
    if (t == 0) g_rn[b] = ss2;
    float mu2 = ss * (1.0f / ND);
    float var2 = ss2 * (1.0f / ND) - mu2 * mu2;
    float rstd2 = rsqrtf(var2 + EPSN);
    float2 qo;
    qo.x = (v0 - mu2) * rstd2;
    qo.y = (v1 - mu2) * rstd2;
    *(float2*)&q_out[(size_t)b * ND + t * 2] = qo;
}

// ---------------------------------------------------------------------------
extern "C" void kernel_launch(void* const* d_in, const int* in_sizes, int n_in,
                              void* d_out, int out_size) {
    const float* features = (const float*)d_in[0];
    const float* Wp       = (const float*)d_in[1];
    const float* bproj    = (const float*)d_in[2];
    const float* lng      = (const float*)d_in[3];
    const float* lnb      = (const float*)d_in[4];
    const float* cbs      = (const float*)d_in[5];
    const float* scales   = (const float*)d_in[6];
    const float* temp     = (const float*)d_in[7];
    float* out = (float*)d_out;
    float* out_q = out + (size_t)NB * NL * NK;

    float *dy, *drn, *dcn;
    __nv_bfloat16 *dfh, *dfl, *dwh, *dwl, *dxh, *dxl, *dch, *dcl;
    cudaGetSymbolAddress((void**)&dy, g_y);
    cudaGetSymbolAddress((void**)&drn, g_rn);
    cudaGetSymbolAddress((void**)&dcn, g_cn);
    cudaGetSymbolAddress((void**)&dfh, g_fh);
    cudaGetSymbolAddress((void**)&dfl, g_fl);
    cudaGetSymbolAddress((void**)&dwh, g_wh);
    cudaGetSymbolAddress((void**)&dwl, g_wl);
    cudaGetSymbolAddress((void**)&dxh, g_xh);
    cudaGetSymbolAddress((void**)&dxl, g_xl);
    cudaGetSymbolAddress((void**)&dch, g_ch);
    cudaGetSymbolAddress((void**)&dcl, g_cl);

    cudaFuncSetAttribute(gemm_mma<0>, cudaFuncAttributeMaxDynamicSharedMemorySize, SMEM_TOTAL);
    cudaFuncSetAttribute(gemm_mma<1>, cudaFuncAttributeMaxDynamicSharedMemorySize, SMEM_TOTAL);

    // 0. preconvert features and W_proj to bf16 hi/lo
    conv_kernel<<<NB * ND / 1024, 256>>>(features, dfh, dfl);
    conv_kernel<<<ND * ND / 1024, 256>>>(Wp, dwh, dwl);
    // 1. proj GEMM: g_y = features @ W^T + b
    {
        dim3 grid(ND / BN, NB / BM);
        gemm_mma<0><<<grid, 256, SMEM_TOTAL>>>(dfh, dfl, dwh, dwl, dy, ND, bproj,
                                               nullptr, nullptr, nullptr, nullptr);
    }
    // 2. fused LN + ReLU (-> x hi/lo) + LN2 + rownorm
    ln_kernel<<<NB, 256>>>(lng, lnb, scales, out_q);
    // 3. codebook norms + level-0 codebook hi/lo
    cbnorm_kernel<<<(NL * NK) / 8, 256>>>(cbs, dcn);
    // 4. level-0 logits GEMM + fused distance epilogue + fused level1-3 fill
    {
        dim3 grid(NK / BN, NB / BM);
        gemm_mma<1><<<grid, 256, SMEM_TOTAL>>>(dxh, dxl, dch, dcl, out, NL * NK,
                                               nullptr, drn, dcn, scales, temp);
    }
}

// round 6
// speedup vs baseline: 3.3349x; 1.2264x over previous
#include <cuda_runtime.h>
#include <cuda_bf16.h>
#include <cstdint>

#define NB 8192
#define ND 512
#define NK 2048
#define NL 4
#define EPSN 1e-5f
#define TEMP_MIN 0.01f

// GEMM: tile 128x128, 256 threads, BK=32, 3-stage cp.async pipeline
#define BM 128
#define BN 128
#define BK 32

// Scratch (static device arrays; no allocations)
static __device__ float g_y[NB * ND];
static __device__ __align__(16) __nv_bfloat16 g_fh[NB * ND];   // features hi
static __device__ __align__(16) __nv_bfloat16 g_fl[NB * ND];   // features lo
static __device__ __align__(16) __nv_bfloat16 g_wh[ND * ND];   // W_proj hi
static __device__ __align__(16) __nv_bfloat16 g_wl[ND * ND];   // W_proj lo
static __device__ __align__(16) __nv_bfloat16 g_xh[NB * ND];   // x hi
static __device__ __align__(16) __nv_bfloat16 g_xl[NB * ND];   // x lo
static __device__ __align__(16) __nv_bfloat16 g_ch[NK * ND];   // codebook0 hi
static __device__ float g_rn[NB];
static __device__ float g_cn[NL * NK];

// ---------------------------------------------------------------------------
__device__ __forceinline__ uint32_t smem_u32(const void* p) {
    uint32_t a;
    asm("{ .reg .u64 t; cvta.to.shared.u64 t, %1; cvt.u32.u64 %0, t; }" : "=r"(a) : "l"(p));
    return a;
}

#define CPA(dst, src) \
    asm volatile("cp.async.cg.shared.global [%0], [%1], 16;" :: "r"(dst), "l"(src) : "memory")
#define CPA_COMMIT() asm volatile("cp.async.commit_group;" ::: "memory")
#define CPA_WAIT(N)  asm volatile("cp.async.wait_group %0;" :: "n"(N) : "memory")

__device__ __forceinline__ void ldm_x4(uint32_t* r, uint32_t addr) {
    asm volatile("ldmatrix.sync.aligned.m8n8.x4.shared.b16 {%0,%1,%2,%3}, [%4];"
                 : "=r"(r[0]), "=r"(r[1]), "=r"(r[2]), "=r"(r[3]) : "r"(addr));
}

__device__ __forceinline__ void mma16816(float* c, const uint32_t* a, const uint32_t* b) {
    asm volatile(
        "mma.sync.aligned.m16n8k16.row.col.f32.bf16.bf16.f32 "
        "{%0,%1,%2,%3}, {%4,%5,%6,%7}, {%8,%9}, {%0,%1,%2,%3};"
        : "+f"(c[0]), "+f"(c[1]), "+f"(c[2]), "+f"(c[3])
        : "r"(a[0]), "r"(a[1]), "r"(a[2]), "r"(a[3]), "r"(b[0]), "r"(b[1]));
}

__device__ __forceinline__ void cvt4(float4 v, uint2& h, uint2& l) {
    __nv_bfloat162 h0 = __floats2bfloat162_rn(v.x, v.y);
    __nv_bfloat162 h1 = __floats2bfloat162_rn(v.z, v.w);
    float lx = v.x - __bfloat162float(h0.x);
    float ly = v.y - __bfloat162float(h0.y);
    float lz = v.z - __bfloat162float(h1.x);
    float lw = v.w - __bfloat162float(h1.y);
    __nv_bfloat162 l0 = __floats2bfloat162_rn(lx, ly);
    __nv_bfloat162 l1 = __floats2bfloat162_rn(lz, lw);
    h.x = *(uint32_t*)&h0; h.y = *(uint32_t*)&h1;
    l.x = *(uint32_t*)&l0; l.y = *(uint32_t*)&l1;
}

// swizzled smem byte offset for (row, 16B-chunk cc) in a 128x64B array
__device__ __forceinline__ uint32_t swz(int row, int cc) {
    return (uint32_t)(row * 64 + ((cc ^ ((row >> 1) & 3)) << 4));
}

// ---------------------------------------------------------------------------
// Split-bf16 tensor GEMM on preconverted operands.
// MODE 0 (proj): 3-pass (Ah,Al,Bh,Bl), +bias epilogue.
// MODE 1 (dist): 2-pass (Ah,Al,Bh),   logits epilogue + fused level1-3 fill.
// ---------------------------------------------------------------------------
template <int MODE>
__global__ void __launch_bounds__(256, 2) gemm_mma(
    const __nv_bfloat16* __restrict__ Ah_g, const __nv_bfloat16* __restrict__ Al_g,
    const __nv_bfloat16* __restrict__ Bh_g, const __nv_bfloat16* __restrict__ Bl_g,
    float* __restrict__ C, int ldc,
    const float* __restrict__ bias, const float* __restrict__ rn,
    const float* __restrict__ cn, const float* __restrict__ scales,
    const float* __restrict__ temp) {
    constexpr int NARR = (MODE == 0) ? 4 : 3;
    constexpr int STAGE_B = NARR * 8192;
    extern __shared__ char sm_[];
    const int tid = threadIdx.x;
    const int wid = tid >> 5, lane = tid & 31;
    const int bm = blockIdx.y * BM, bn = blockIdx.x * BN;
    const int wm = (wid & 1) * 64;
    const int wn = (wid >> 1) * 32;
    const uint32_t sbase = smem_u32(sm_);

    // staging addresses (per thread): 2 x 16B chunks per array
    const int r0 = tid >> 2, c0 = tid & 3;
    const uint32_t d0 = swz(r0, c0);
    const char* pAh = (const char*)Ah_g + (size_t)(bm + r0) * 1024 + c0 * 16;
    const char* pAl = (const char*)Al_g + (size_t)(bm + r0) * 1024 + c0 * 16;
    const char* pBh = (const char*)Bh_g + (size_t)(bn + r0) * 1024 + c0 * 16;
    const char* pBl = (MODE == 0) ? (const char*)Bl_g + (size_t)(bn + r0) * 1024 + c0 * 16
                                  : nullptr;

    float acc[4][4][4];
#pragma unroll
    for (int mi = 0; mi < 4; mi++)
#pragma unroll
        for (int ni = 0; ni < 4; ni++)
#pragma unroll
            for (int j = 0; j < 4; j++) acc[mi][ni][j] = 0.f;

    const int arow = lane & 15, asel = lane >> 4;
    const int brow = ((lane >> 4) << 3) + (lane & 7);
    const int bsel = (lane >> 3) & 1;

    auto issue_stage = [&](uint32_t sb, int koff) {
        CPA(sb + d0,                 pAh + koff);
        CPA(sb + d0 + 4096,          pAh + koff + 65536);
        CPA(sb + 8192 + d0,          pAl + koff);
        CPA(sb + 8192 + d0 + 4096,   pAl + koff + 65536);
        CPA(sb + 16384 + d0,         pBh + koff);
        CPA(sb + 16384 + d0 + 4096,  pBh + koff + 65536);
        if (MODE == 0) {
            CPA(sb + 24576 + d0,         pBl + koff);
            CPA(sb + 24576 + d0 + 4096,  pBl + koff + 65536);
        }
        CPA_COMMIT();
    };

    const int NCH = ND / BK;  // 16
    issue_stage(sbase, 0);
    issue_stage(sbase + STAGE_B, 64);

#pragma unroll 1
    for (int kc = 0; kc < NCH; kc++) {
        if (kc + 2 < NCH) {
            CPA_WAIT(1);
            __syncthreads();
            int s = (kc + 2) % 3;
            issue_stage(sbase + s * STAGE_B, (kc + 2) * 64);
        } else if (kc + 1 < NCH) {
            CPA_WAIT(1);
            __syncthreads();
        } else {
            CPA_WAIT(0);
            __syncthreads();
        }
        const uint32_t ah = sbase + (kc % 3) * STAGE_B;
        const uint32_t al = ah + 8192;
        const uint32_t bh = ah + 16384;
        const uint32_t bl = ah + 24576;
#pragma unroll
        for (int ks = 0; ks < 2; ks++) {
            const int ccA = ks * 2 + asel;
            const int ccB = ks * 2 + bsel;
            uint32_t bfh[4][2], bfl[4][2];
            {
                int rb = wn + brow;
                uint32_t o1 = swz(rb, ccB), o2 = swz(rb + 16, ccB);
                uint32_t t4[4];
                ldm_x4(t4, bh + o1);
                bfh[0][0] = t4[0]; bfh[0][1] = t4[1]; bfh[1][0] = t4[2]; bfh[1][1] = t4[3];
                ldm_x4(t4, bh + o2);
                bfh[2][0] = t4[0]; bfh[2][1] = t4[1]; bfh[3][0] = t4[2]; bfh[3][1] = t4[3];
                if (MODE == 0) {
                    ldm_x4(t4, bl + o1);
                    bfl[0][0] = t4[0]; bfl[0][1] = t4[1]; bfl[1][0] = t4[2]; bfl[1][1] = t4[3];
                    ldm_x4(t4, bl + o2);
                    bfl[2][0] = t4[0]; bfl[2][1] = t4[1]; bfl[3][0] = t4[2]; bfl[3][1] = t4[3];
                }
            }
#pragma unroll
            for (int mi = 0; mi < 4; mi++) {
                int ra = wm + mi * 16 + arow;
                uint32_t ao = swz(ra, ccA);
                uint32_t afh[4];
                ldm_x4(afh, ah + ao);
#pragma unroll
                for (int ni = 0; ni < 4; ni++) mma16816(acc[mi][ni], afh, bfh[ni]);
                if (MODE == 0) {
#pragma unroll
                    for (int ni = 0; ni < 4; ni++) mma16816(acc[mi][ni], afh, bfl[ni]);
                }
                uint32_t afl[4];
                ldm_x4(afl, al + ao);
#pragma unroll
                for (int ni = 0; ni < 4; ni++) mma16816(acc[mi][ni], afl, bfh[ni]);
            }
        }
    }
    __syncthreads();

    // Epilogue
    const int gid = lane >> 2, t4i = lane & 3;
    float s0 = 0.f, invt = 0.f;
    if (MODE == 1) {
        s0 = scales[0];
        invt = 1.0f / fmaxf(temp[0], TEMP_MIN);
    }

    float* sval = (float*)sm_;
    if (MODE == 1) {
        int cbase = NK + blockIdx.x * 384;  // 6144 / 16 x-tiles
        for (int i = tid; i < 384; i += 256) sval[i] = -cn[cbase + i] * invt;
        __syncthreads();
    }

#pragma unroll
    for (int mi = 0; mi < 4; mi++) {
        int r = bm + wm + mi * 16 + gid;
#pragma unroll
        for (int ni = 0; ni < 4; ni++) {
            int c = bn + wn + ni * 8 + t4i * 2;
            float* a4 = acc[mi][ni];
            if (MODE == 0) {
                float b0 = bias[c], b1 = bias[c + 1];
                *(float2*)&C[(size_t)r * ldc + c] = make_float2(a4[0] + b0, a4[1] + b1);
                *(float2*)&C[(size_t)(r + 8) * ldc + c] = make_float2(a4[2] + b0, a4[3] + b1);
            } else {
                float m2s = 2.0f * s0;
                float cv0 = cn[c], cv1 = cn[c + 1];
                float rv0 = rn[r], rv1 = rn[r + 8];
                float2 o0, o1;
                o0.x = -(rv0 + cv0 - m2s * a4[0]) * invt;
                o0.y = -(rv0 + cv1 - m2s * a4[1]) * invt;
                o1.x = -(rv1 + cv0 - m2s * a4[2]) * invt;
                o1.y = -(rv1 + cv1 - m2s * a4[3]) * invt;
                __stcs((float2*)&C[(size_t)r * ldc + c], o0);
                __stcs((float2*)&C[(size_t)(r + 8) * ldc + c], o1);
            }
        }
    }

    // Fused levels 1..3 fill: 128 rows x 384 cols per CTA (streaming stores)
    if (MODE == 1) {
        int fbase = NK + blockIdx.x * 384;
#pragma unroll
        for (int j = 0; j < 48; j++) {
            int idx = tid + j * 256;  // 12288 float4 per CTA
            int row = idx / 96;
            int cc = (idx - row * 96) * 4;
            float4 v = *(float4*)&sval[cc];
            __stcs((float4*)&C[(size_t)(bm + row) * ldc + fbase + cc], v);
        }
    }
}

// ---------------------------------------------------------------------------
// fp32 -> bf16 hi/lo converter (elementwise, float4 per thread)
// ---------------------------------------------------------------------------
__global__ void __launch_bounds__(256) conv_kernel(const float* __restrict__ src,
                                                   __nv_bfloat16* __restrict__ h,
                                                   __nv_bfloat16* __restrict__ l) {
    int idx = blockIdx.x * 256 + threadIdx.x;
    float4 v = ((const float4*)src)[idx];
    uint2 hh, ll;
    cvt4(v, hh, ll);
    ((uint2*)h)[idx] = hh;
    ((uint2*)l)[idx] = ll;
}

// ---------------------------------------------------------------------------
// Codebook norms + level-0 hi conversion (lo no longer needed)
// ---------------------------------------------------------------------------
__global__ void __launch_bounds__(256) cbnorm_kernel(const float* __restrict__ cb,
                                                     float* __restrict__ cn) {
    int row = blockIdx.x * 8 + (threadIdx.x >> 5);
    int lane = threadIdx.x & 31;
    const float* p = cb + (size_t)row * ND;
    float s = 0.f;
#pragma unroll
    for (int i = 0; i < 4; i++) {
        int off = (lane + i * 32) * 4;
        float4 v = *(const float4*)&p[off];
        s += v.x * v.x + v.y * v.y + v.z * v.z + v.w * v.w;
        if (row < NK) {
            __nv_bfloat162 h0 = __floats2bfloat162_rn(v.x, v.y);
            __nv_bfloat162 h1 = __floats2bfloat162_rn(v.z, v.w);
            uint2 hh;
            hh.x = *(uint32_t*)&h0; hh.y = *(uint32_t*)&h1;
            *(uint2*)&g_ch[(size_t)row * ND + off] = hh;
        }
    }
#pragma unroll
    for (int o = 16; o > 0; o >>= 1) s += __shfl_xor_sync(0xffffffffu, s, o);
    if (lane == 0) cn[row] = s;
}

// ---------------------------------------------------------------------------
// Warp-per-row fused LN(affine)+ReLU -> x hi/lo, LN2 (no affine), row norm.
// Block = 8 warps = 8 rows; no __syncthreads.
// ---------------------------------------------------------------------------
__global__ void __launch_bounds__(256) ln_kernel(const float* __restrict__ lng,
                                                 const float* __restrict__ lnb,
                                                 const float* __restrict__ scales,
                                                 float* __restrict__ q_out) {
    int b = blockIdx.x * 8 + (threadIdx.x >> 5);
    int lane = threadIdx.x & 31;
    const float* y = g_y + (size_t)b * ND;

    float4 v[4];
    float s = 0.f, s2 = 0.f;
#pragma unroll
    for (int i = 0; i < 4; i++) {
        v[i] = *(const float4*)&y[(lane + i * 32) * 4];
        s += v[i].x + v[i].y + v[i].z + v[i].w;
        s2 += v[i].x * v[i].x + v[i].y * v[i].y + v[i].z * v[i].z + v[i].w * v[i].w;
    }
#pragma unroll
    for (int o = 16; o > 0; o >>= 1) {
        s += __shfl_xor_sync(0xffffffffu, s, o);
        s2 += __shfl_xor_sync(0xffffffffu, s2, o);
    }
    float mu = s * (1.0f / ND);
    float var = s2 * (1.0f / ND) - mu * mu;
    float rstd = rsqrtf(var + EPSN);

    float x[16];
    float ss = 0.f, ss2 = 0.f;
    float s0 = scales[0];
#pragma unroll
    for (int i = 0; i < 4; i++) {
        int off = (lane + i * 32) * 4;
        float4 g = *(const float4*)&lng[off];
        float4 bb = *(const float4*)&lnb[off];
        float* vi = &v[i].x;
        float* gi = &g.x;
        float* bi = &bb.x;
#pragma unroll
        for (int j = 0; j < 4; j++) {
            float xv = fmaxf((vi[j] - mu) * rstd * gi[j] + bi[j], 0.0f);
            x[i * 4 + j] = xv;
            float sv = s0 * xv;
            ss += sv;
            ss2 += sv * sv;
        }
        // bf16 hi/lo
        __nv_bfloat162 h0 = __floats2bfloat162_rn(x[i * 4], x[i * 4 + 1]);
        __nv_bfloat162 h1 = __floats2bfloat162_rn(x[i * 4 + 2], x[i * 4 + 3]);
        float l0 = x[i * 4] - __bfloat162float(h0.x);
        float l1 = x[i * 4 + 1] - __bfloat162float(h0.y);
        float l2 = x[i * 4 + 2] - __bfloat162float(h1.x);
        float l3 = x[i * 4 + 3] - __bfloat162float(h1.y);
        __nv_bfloat162 lo0 = __floats2bfloat162_rn(l0, l1);
        __nv_bfloat162 lo1 = __floats2bfloat162_rn(l2, l3);
        uint2 hh, ll;
        hh.x = *(uint32_t*)&h0; hh.y = *(uint32_t*)&h1;
        ll.x = *(uint32_t*)&lo0; ll.y = *(uint32_t*)&lo1;
        *(uint2*)&g_xh[(size_t)b * ND + off] = hh;
        *(uint2*)&g_xl[(size_t)b * ND + off] = ll;
    }
#pragma unroll
    for (int o = 16; o > 0; o >>= 1) {
        ss += __shfl_xor_sync(0xffffffffu, ss, o);
        ss2 += __shfl_xor_sync(0xffffffffu, ss2, o);
    }
    if (lane == 0) g_rn[b] = ss2;
    float mu2 = ss * (1.0f / ND);
    float var2 = ss2 * (1.0f / ND) - mu2 * mu2;
    float rstd2 = rsqrtf(var2 + EPSN);
#pragma unroll
    for (int i = 0; i < 4; i++) {
        int off = (lane + i * 32) * 4;
        float4 qo;
        qo.x = (s0 * x[i * 4 + 0] - mu2) * rstd2;
        qo.y = (s0 * x[i * 4 + 1] - mu2) * rstd2;
        qo.z = (s0 * x[i * 4 + 2] - mu2) * rstd2;
        qo.w = (s0 * x[i * 4 + 3] - mu2) * rstd2;
        *(float4*)&q_out[(size_t)b * ND + off] = qo;
    }
}

// ---------------------------------------------------------------------------
extern "C" void kernel_launch(void* const* d_in, const int* in_sizes, int n_in,
                              void* d_out, int out_size) {
    const float* features = (const float*)d_in[0];
    const float* Wp       = (const float*)d_in[1];
    const float* bproj    = (const float*)d_in[2];
    const float* lng      = (const float*)d_in[3];
    const float* lnb      = (const float*)d_in[4];
    const float* cbs      = (const float*)d_in[5];
    const float* scales   = (const float*)d_in[6];
    const float* temp     = (const float*)d_in[7];
    float* out = (float*)d_out;
    float* out_q = out + (size_t)NB * NL * NK;

    float *dy, *drn, *dcn;
    __nv_bfloat16 *dfh, *dfl, *dwh, *dwl, *dxh, *dxl, *dch;
    cudaGetSymbolAddress((void**)&dy, g_y);
    cudaGetSymbolAddress((void**)&drn, g_rn);
    cudaGetSymbolAddress((void**)&dcn, g_cn);
    cudaGetSymbolAddress((void**)&dfh, g_fh);
    cudaGetSymbolAddress((void**)&dfl, g_fl);
    cudaGetSymbolAddress((void**)&dwh, g_wh);
    cudaGetSymbolAddress((void**)&dwl, g_wl);
    cudaGetSymbolAddress((void**)&dxh, g_xh);
    cudaGetSymbolAddress((void**)&dxl, g_xl);
    cudaGetSymbolAddress((void**)&dch, g_ch);

    cudaFuncSetAttribute(gemm_mma<0>, cudaFuncAttributeMaxDynamicSharedMemorySize, 3 * 32768);
    cudaFuncSetAttribute(gemm_mma<1>, cudaFuncAttributeMaxDynamicSharedMemorySize, 3 * 24576);

    // 0. preconvert features and W_proj to bf16 hi/lo
    conv_kernel<<<NB * ND / 1024, 256>>>(features, dfh, dfl);
    conv_kernel<<<ND * ND / 1024, 256>>>(Wp, dwh, dwl);
    // 1. proj GEMM (3-pass): g_y = features @ W^T + b
    {
        dim3 grid(ND / BN, NB / BM);
        gemm_mma<0><<<grid, 256, 3 * 32768>>>(dfh, dfl, dwh, dwl, dy, ND, bproj,
                                              nullptr, nullptr, nullptr, nullptr);
    }
    // 2. fused LN + ReLU (-> x hi/lo) + LN2 + rownorm (warp per row)
    ln_kernel<<<NB / 8, 256>>>(lng, lnb, scales, out_q);
    // 3. codebook norms + level-0 codebook hi
    cbnorm_kernel<<<(NL * NK) / 8, 256>>>(cbs, dcn);
    // 4. level-0 logits GEMM (2-pass) + fused epilogue + fused fill
    {
        dim3 grid(NK / BN, NB / BM);
        gemm_mma<1><<<grid, 256, 3 * 24576>>>(dxh, dxl, dch, nullptr, out, NL * NK,
                                              nullptr, drn, dcn, scales, temp);
    }
}